// round 12
// baseline (speedup 1.0000x reference)
#include <cuda_runtime.h>
#include <cuda_bf16.h>
#include <cstdint>

#define Hh    51
#define GP    56          // padded rows per gate
#define NRW   224         // 4*GP weight rows
#define Mt    64          // batch tile
#define XCOL  56          // K index of the x input column (h: 0..50, pad 51..55)
#define SPB   144         // row stride in bytes (72 bf16) — conflict-free ldmatrix
#define Tt    2048
#define OTot  2112
#define Bt    8192
#define GRID  148
#define TPB   448         // 14 warps: (pw 0..1 teams) x (jt 0..6)

#define WBYTES (NRW*SPB)                 // 32256 per weight tile
#define OFF_W1H 0
#define OFF_W1L (OFF_W1H + WBYTES)
#define OFF_W2H (OFF_W1L + WBYTES)
#define OFF_W2L (OFF_W2H + WBYTES)
#define OFF_AH  (OFF_W2L + WBYTES)      // 129024
#define OFF_AL  (OFF_AH + Mt*SPB)       // +9216
#define OFF_PARTS (OFF_AL + Mt*SPB)     // f32[14][32]
#define SMEM_BYTES (OFF_PARTS + 14*32*4)

// per-team barrier: 7 warps = 224 threads, barrier id = team+1
#define TEAM_BAR(team) \
    asm volatile("bar.sync %0, 224;" :: "r"((team)+1) : "memory")

static __device__ __forceinline__ uint32_t smem_u32(const void* p){
    uint32_t a;
    asm("{ .reg .u64 t; cvta.to.shared.u64 t, %1; cvt.u32.u64 %0, t; }"
        : "=r"(a) : "l"(p));
    return a;
}

__device__ __forceinline__ void lda(uint32_t (&r)[4], uint32_t base, int mt, int kc, int lane){
    uint32_t addr = base + (uint32_t)((mt*16 + ((lane>>3)&1)*8 + (lane&7))*SPB
                                      + kc*32 + ((lane>>4)&1)*16);
    asm volatile("ldmatrix.sync.aligned.m8n8.x4.shared.b16 {%0,%1,%2,%3}, [%4];"
        : "=r"(r[0]),"=r"(r[1]),"=r"(r[2]),"=r"(r[3]) : "r"(addr));
}
__device__ __forceinline__ void ldb(uint32_t (&r)[2], uint32_t base, int nbase, int kc, int lane){
    int l = lane & 15;
    uint32_t addr = base + (uint32_t)((nbase + (l&7))*SPB + kc*32 + ((l>>3)&1)*16);
    asm volatile("ldmatrix.sync.aligned.m8n8.x2.shared.b16 {%0,%1}, [%2];"
        : "=r"(r[0]),"=r"(r[1]) : "r"(addr));
}
__device__ __forceinline__ void mma_bf16(float (&d)[4], const uint32_t (&a)[4],
                                         const uint32_t (&b)[2]){
    asm volatile("mma.sync.aligned.m16n8k16.row.col.f32.bf16.bf16.f32 "
        "{%0,%1,%2,%3}, {%4,%5,%6,%7}, {%8,%9}, {%0,%1,%2,%3};"
        : "+f"(d[0]),"+f"(d[1]),"+f"(d[2]),"+f"(d[3])
        : "r"(a[0]),"r"(a[1]),"r"(a[2]),"r"(a[3]), "r"(b[0]),"r"(b[1]));
}

__device__ __forceinline__ float sigm(float x){
    return __fdividef(1.0f, 1.0f + __expf(-x));
}
__device__ __forceinline__ float tanh_f(float x){
    float ax = fabsf(x);
    float e  = __expf(-2.0f * ax);
    float r  = __fdividef(1.0f - e, 1.0f + e);
    return copysignf(r, x);
}
__device__ __forceinline__ void split_sts(char* smem, int off_h, int off_l,
                                          uint32_t o, float v){
    __nv_bfloat16 hi = __float2bfloat16(v);
    float lo = v - __bfloat162float(hi);
    *reinterpret_cast<__nv_bfloat16*>(smem + off_h + o) = hi;
    *reinterpret_cast<__nv_bfloat16*>(smem + off_l + o) = __float2bfloat16(lo);
}

// One layer's MMA for this warp: D[cb][gate][4] += A(hi,lo) x W(hi,lo), 3-product split.
__device__ __forceinline__ void layer_mma(float (&D)[2][4][4],
    uint32_t aH, uint32_t aL, uint32_t wH, uint32_t wL,
    int pw, int jt, int lane)
{
    #pragma unroll
    for (int cb = 0; cb < 2; cb++)
        #pragma unroll
        for (int g = 0; g < 4; g++)
            #pragma unroll
            for (int i = 0; i < 4; i++) D[cb][g][i] = 0.f;

    #pragma unroll
    for (int kc = 0; kc < 4; kc++){
        uint32_t ah0[4], al0[4], ah1[4], al1[4];
        lda(ah0, aH, pw*2,   kc, lane);
        lda(al0, aL, pw*2,   kc, lane);
        lda(ah1, aH, pw*2+1, kc, lane);
        lda(al1, aL, pw*2+1, kc, lane);
        #pragma unroll
        for (int g = 0; g < 4; g++){
            uint32_t bh[2], bl[2];
            ldb(bh, wH, g*GP + jt*8, kc, lane);
            ldb(bl, wL, g*GP + jt*8, kc, lane);
            mma_bf16(D[0][g], ah0, bh);
            mma_bf16(D[0][g], ah0, bl);
            mma_bf16(D[0][g], al0, bh);
            mma_bf16(D[1][g], ah1, bh);
            mma_bf16(D[1][g], ah1, bl);
            mma_bf16(D[1][g], al1, bh);
        }
    }
}

__global__ void __launch_bounds__(TPB, 1)
lstm_hmma_kernel(
    const float* __restrict__ x,
    const float* __restrict__ Wih1, const float* __restrict__ Whh1,
    const float* __restrict__ bih1, const float* __restrict__ bhh1,
    const float* __restrict__ Wih2, const float* __restrict__ Whh2,
    const float* __restrict__ bih2, const float* __restrict__ bhh2,
    const float* __restrict__ Wout, const float* __restrict__ bout,
    float* __restrict__ out)
{
    extern __shared__ char smem[];
    uint32_t sb = smem_u32(smem);
    int tid = threadIdx.x, w = tid >> 5, lane = tid & 31;

    // ---- weights into smem: row n = gate*56 + j, K-major, bf16 hi/lo ----
    for (int idx = tid; idx < NRW*64; idx += TPB){
        int n = idx >> 6, k = idx & 63;
        int g = n / GP, j = n - g*GP;
        float w1 = 0.f, w2 = 0.f;
        if (j < Hh){
            if (k < Hh){
                int src = (g*Hh + j)*Hh + k;
                w1 = Whh1[src];
                w2 = Wih2[src] + Whh2[src];
            } else if (k == XCOL){
                w1 = Wih1[g*Hh + j];
            }
        }
        uint32_t o = (uint32_t)(n*SPB + k*2);
        split_sts(smem, OFF_W1H, OFF_W1L, o, w1);
        split_sts(smem, OFF_W2H, OFF_W2L, o, w2);
    }
    // zero A tiles (both splits, incl. pad bytes)
    for (int idx = tid; idx < 2*Mt*SPB/4; idx += TPB)
        *reinterpret_cast<uint32_t*>(smem + OFF_AH + idx*4) = 0u;
    __syncthreads();

    // batch range (balanced across 148 CTAs; nb = 55 or 56)
    int bstart = (int)(((long long)blockIdx.x       * Bt) / GRID);
    int bend   = (int)(((long long)(blockIdx.x + 1) * Bt) / GRID);
    int nb     = bend - bstart;

    // x(0) into A col XCOL
    if (tid < Mt){
        float xv = (tid < nb) ? __ldg(&x[(size_t)(bstart + tid) * Tt]) : 0.f;
        split_sts(smem, OFF_AH, OFF_AL, (uint32_t)(tid*SPB + XCOL*2), xv);
    }
    __syncthreads();

    // ---- per-thread mapping ----
    int pw = w / 7, jt = w - pw*7;       // pw: team (M half), jt: j-tile
    int rgrp = lane >> 2;
    int j0 = jt*8 + 2*(lane & 3);
    int j1 = j0 + 1;

    float b1r[4][2], b2r[4][2], wor[2];
    #pragma unroll
    for (int g = 0; g < 4; g++){
        b1r[g][0] = (j0 < Hh) ? (bih1[g*Hh + j0] + bhh1[g*Hh + j0]) : 0.f;
        b1r[g][1] = (j1 < Hh) ? (bih1[g*Hh + j1] + bhh1[g*Hh + j1]) : 0.f;
        b2r[g][0] = (j0 < Hh) ? (bih2[g*Hh + j0] + bhh2[g*Hh + j0]) : 0.f;
        b2r[g][1] = (j1 < Hh) ? (bih2[g*Hh + j1] + bhh2[g*Hh + j1]) : 0.f;
    }
    wor[0] = (j0 < Hh) ? Wout[j0] : 0.f;
    wor[1] = (j1 < Hh) ? Wout[j1] : 0.f;

    float c1[2][2][2];                   // [cb][m-half][j-col]
    #pragma unroll
    for (int a = 0; a < 2; a++)
        #pragma unroll
        for (int b = 0; b < 2; b++)
            #pragma unroll
            for (int c = 0; c < 2; c++) c1[a][b][c] = 0.f;

    float bo = *bout;
    float* parts = reinterpret_cast<float*>(smem + OFF_PARTS);
    bool ywarp = (jt == 0);
    int ym = pw*32 + lane;               // y-warp's batch row within A tile

    for (int t = 0; t < OTot; t++){
        // prefetch next x (y-warps only)
        float xnext = 0.f;
        if (ywarp && (t + 1 < Tt) && (ym < nb))
            xnext = __ldg(&x[(size_t)(bstart + ym) * Tt + t + 1]);

        float D[2][4][4];

        // ================= layer 1 =================
        layer_mma(D, sb + OFF_AH, sb + OFF_AL, sb + OFF_W1H, sb + OFF_W1L, pw, jt, lane);

        #pragma unroll
        for (int cb = 0; cb < 2; cb++){
            int mbase = (pw*2 + cb)*16 + rgrp;
            #pragma unroll
            for (int hf = 0; hf < 2; hf++){
                int m = mbase + hf*8;
                #pragma unroll
                for (int jc = 0; jc < 2; jc++){
                    int e = hf*2 + jc;
                    float gi = D[cb][0][e] + b1r[0][jc];
                    float gf = D[cb][1][e] + b1r[1][jc];
                    float gg = D[cb][2][e] + b1r[2][jc];
                    float go = D[cb][3][e] + b1r[3][jc];
                    float cn = sigm(gf)*c1[cb][hf][jc] + sigm(gi)*tanh_f(gg);
                    c1[cb][hf][jc] = cn;
                    float hp = sigm(go)*tanh_f(cn);
                    int j = jc ? j1 : j0;
                    split_sts(smem, OFF_AH, OFF_AL, (uint32_t)(m*SPB + j*2), hp);
                }
            }
        }
        TEAM_BAR(pw);

        // ================= layer 2 (emit) =================
        layer_mma(D, sb + OFF_AH, sb + OFF_AL, sb + OFF_W2H, sb + OFF_W2L, pw, jt, lane);

        #pragma unroll
        for (int cb = 0; cb < 2; cb++){
            float plo = 0.f, phi = 0.f;
            #pragma unroll
            for (int hf = 0; hf < 2; hf++){
                #pragma unroll
                for (int jc = 0; jc < 2; jc++){
                    int e = hf*2 + jc;
                    float gi = D[cb][0][e] + b2r[0][jc];
                    float gf = D[cb][1][e] + b2r[1][jc];
                    float gg = D[cb][2][e] + b2r[2][jc];
                    float go = D[cb][3][e] + b2r[3][jc];
                    float c2 = sigm(gf)*c1[cb][hf][jc] + sigm(gi)*tanh_f(gg);
                    float v  = sigm(go)*tanh_f(c2) * wor[jc];
                    if (hf) phi += v; else plo += v;
                }
            }
            plo += __shfl_xor_sync(0xffffffffu, plo, 1);
            plo += __shfl_xor_sync(0xffffffffu, plo, 2);
            phi += __shfl_xor_sync(0xffffffffu, phi, 1);
            phi += __shfl_xor_sync(0xffffffffu, phi, 2);
            if ((lane & 3) == 0){
                parts[w*32 + cb*16 + rgrp]     = plo;
                parts[w*32 + cb*16 + 8 + rgrp] = phi;
            }
        }
        TEAM_BAR(pw);

        // ---- combine y, emit output, feed back x (team's own y-warp) ----
        if (ywarp){
            float y = bo;
            #pragma unroll
            for (int q = 0; q < 7; q++)
                y += parts[(pw*7 + q)*32 + lane];
            if (ym < nb) out[(size_t)(bstart + ym)*OTot + t] = y;
            float xfb = (t + 1 < Tt) ? xnext : y;
            split_sts(smem, OFF_AH, OFF_AL, (uint32_t)(ym*SPB + XCOL*2), xfb);
        }
        TEAM_BAR(pw);
    }
}

extern "C" void kernel_launch(void* const* d_in, const int* in_sizes, int n_in,
                              void* d_out, int out_size)
{
    const float* x    = (const float*)d_in[0];
    const float* Wih1 = (const float*)d_in[1];
    const float* Whh1 = (const float*)d_in[2];
    const float* bih1 = (const float*)d_in[3];
    const float* bhh1 = (const float*)d_in[4];
    const float* Wih2 = (const float*)d_in[5];
    const float* Whh2 = (const float*)d_in[6];
    const float* bih2 = (const float*)d_in[7];
    const float* bhh2 = (const float*)d_in[8];
    const float* Wout = (const float*)d_in[9];
    const float* bout = (const float*)d_in[10];
    float* out = (float*)d_out;

    cudaFuncSetAttribute(lstm_hmma_kernel,
                         cudaFuncAttributeMaxDynamicSharedMemorySize, SMEM_BYTES);

    lstm_hmma_kernel<<<GRID, TPB, SMEM_BYTES>>>(
        x, Wih1, Whh1, bih1, bhh1, Wih2, Whh2, bih2, bhh2, Wout, bout, out);
}

// round 14
// speedup vs baseline: 1.5829x; 1.5829x over previous
#include <cuda_runtime.h>
#include <cuda_bf16.h>
#include <cstdint>

#define Hh    51
#define GP    56          // padded rows per gate
#define LOFF  224         // rows per layer block (4*GP)
#define NRW   448         // total weight rows (2 layers)
#define Mt    64          // batch tile
#define SPB   144         // row stride bytes (64 bf16 data + pad) — conflict-free ldmatrix
#define Tt    2048
#define OTot  2112
#define Bt    8192
#define GRID  148
#define TPB   448         // 14 warps: (pw 0..1) x (jt 0..6)

#define ATILE  (Mt*SPB)                  // 9216
#define OFF_WH 0
#define OFF_WL (OFF_WH + NRW*SPB)        // 64512
#define OFF_A  (OFF_WL + NRW*SPB)        // 129024: [buf][H,L] -> 4 x 9216
#define OFF_PARTS (OFF_A + 4*ATILE)      // 165888: f32[2][14][32]
#define OFF_XS (OFF_PARTS + 2*14*32*4)   // 169472: f32[2][64]
#define SMEM_BYTES (OFF_XS + 2*64*4)     // 169984

static __device__ __forceinline__ uint32_t smem_u32(const void* p){
    uint32_t a;
    asm("{ .reg .u64 t; cvta.to.shared.u64 t, %1; cvt.u32.u64 %0, t; }"
        : "=r"(a) : "l"(p));
    return a;
}

__device__ __forceinline__ void lda(uint32_t (&r)[4], uint32_t base, int mt, int kc, int lane){
    uint32_t addr = base + (uint32_t)((mt*16 + ((lane>>3)&1)*8 + (lane&7))*SPB
                                      + kc*32 + ((lane>>4)&1)*16);
    asm volatile("ldmatrix.sync.aligned.m8n8.x4.shared.b16 {%0,%1,%2,%3}, [%4];"
        : "=r"(r[0]),"=r"(r[1]),"=r"(r[2]),"=r"(r[3]) : "r"(addr));
}
__device__ __forceinline__ void ldb(uint32_t (&r)[2], uint32_t base, int nbase, int kc, int lane){
    int l = lane & 15;
    uint32_t addr = base + (uint32_t)((nbase + (l&7))*SPB + kc*32 + ((l>>3)&1)*16);
    asm volatile("ldmatrix.sync.aligned.m8n8.x2.shared.b16 {%0,%1}, [%2];"
        : "=r"(r[0]),"=r"(r[1]) : "r"(addr));
}
__device__ __forceinline__ void mma_bf16(float (&d)[4], const uint32_t (&a)[4],
                                         const uint32_t (&b)[2]){
    asm volatile("mma.sync.aligned.m16n8k16.row.col.f32.bf16.bf16.f32 "
        "{%0,%1,%2,%3}, {%4,%5,%6,%7}, {%8,%9}, {%0,%1,%2,%3};"
        : "+f"(d[0]),"+f"(d[1]),"+f"(d[2]),"+f"(d[3])
        : "r"(a[0]),"r"(a[1]),"r"(a[2]),"r"(a[3]), "r"(b[0]),"r"(b[1]));
}

__device__ __forceinline__ float sigm(float x){
    return __fdividef(1.0f, 1.0f + __expf(-x));
}
__device__ __forceinline__ float tanh_f(float x){
    float ax = fabsf(x);
    float e  = __expf(-2.0f * ax);
    float r  = __fdividef(1.0f - e, 1.0f + e);
    return copysignf(r, x);
}
__device__ __forceinline__ void split_sts(char* smem, int off_h, int off_l,
                                          uint32_t o, float v){
    __nv_bfloat16 hi = __float2bfloat16(v);
    float lo = v - __bfloat162float(hi);
    *reinterpret_cast<__nv_bfloat16*>(smem + off_h + o) = hi;
    *reinterpret_cast<__nv_bfloat16*>(smem + off_l + o) = __float2bfloat16(lo);
}

// One layer's GEMM for this warp: D[cb][g][4] = A(hi,lo) x W_L(hi,lo), 3-product split.
template<int L>
__device__ __forceinline__ void layer_mma(float (&D)[2][4][4],
    uint32_t aH, uint32_t aL, uint32_t wH, uint32_t wL,
    int pw, int jt, int lane)
{
    #pragma unroll
    for (int cb = 0; cb < 2; cb++)
        #pragma unroll
        for (int g = 0; g < 4; g++)
            #pragma unroll
            for (int i = 0; i < 4; i++) D[cb][g][i] = 0.f;

    #pragma unroll
    for (int kc = 0; kc < 4; kc++){
        uint32_t ah0[4], al0[4], ah1[4], al1[4];
        lda(ah0, aH, pw*2,   kc, lane);
        lda(al0, aL, pw*2,   kc, lane);
        lda(ah1, aH, pw*2+1, kc, lane);
        lda(al1, aL, pw*2+1, kc, lane);
        #pragma unroll
        for (int g = 0; g < 4; g++){
            int nb_ = L*LOFF + g*GP + jt*8;
            uint32_t bh[2], bl[2];
            ldb(bh, wH, nb_, kc, lane);
            ldb(bl, wL, nb_, kc, lane);
            mma_bf16(D[0][g], ah0, bh);
            mma_bf16(D[0][g], ah0, bl);
            mma_bf16(D[0][g], al0, bh);
            mma_bf16(D[1][g], ah1, bh);
            mma_bf16(D[1][g], ah1, bl);
            mma_bf16(D[1][g], al1, bh);
        }
    }
}

__global__ void __launch_bounds__(TPB, 1)
lstm_hmma_kernel(
    const float* __restrict__ x,
    const float* __restrict__ Wih1, const float* __restrict__ Whh1,
    const float* __restrict__ bih1, const float* __restrict__ bhh1,
    const float* __restrict__ Wih2, const float* __restrict__ Whh2,
    const float* __restrict__ bih2, const float* __restrict__ bhh2,
    const float* __restrict__ Wout, const float* __restrict__ bout,
    float* __restrict__ out)
{
    extern __shared__ char smem[];
    uint32_t sb = smem_u32(smem);
    int tid = threadIdx.x, w = tid >> 5, lane = tid & 31;

    // ---- weights: row n = L*224 + gate*56 + j, K-major (no x column), hi/lo ----
    for (int idx = tid; idx < NRW*64; idx += TPB){
        int n = idx >> 6, k = idx & 63;
        int L = n / LOFF, r = n - L*LOFF;
        int g = r / GP, j = r - g*GP;
        float wv = 0.f;
        if (j < Hh && k < Hh){
            int src = (g*Hh + j)*Hh + k;
            wv = L ? (Wih2[src] + Whh2[src]) : Whh1[src];
        }
        split_sts(smem, OFF_WH, OFF_WL, (uint32_t)(n*SPB + k*2), wv);
    }
    // zero both A buffers (hi+lo)
    for (int idx = tid; idx < 4*ATILE/4; idx += TPB)
        *reinterpret_cast<uint32_t*>(smem + OFF_A + idx*4) = 0u;

    int bstart = (int)(((long long)blockIdx.x       * Bt) / GRID);
    int bend   = (int)(((long long)(blockIdx.x + 1) * Bt) / GRID);
    int nb     = bend - bstart;

    float* xs    = reinterpret_cast<float*>(smem + OFF_XS);     // [2][64]
    float* parts = reinterpret_cast<float*>(smem + OFF_PARTS);  // [2][14*32]
    if (tid < Mt)
        xs[tid] = (tid < nb) ? __ldg(&x[(size_t)(bstart + tid) * Tt]) : 0.f;
    __syncthreads();

    // ---- per-thread mapping ----
    int pw = w / 7, jt = w - pw*7;
    int rgrp = lane >> 2;
    int j0 = jt*8 + 2*(lane & 3);
    int j1 = j0 + 1;

    float b1r[4][2], b2r[4][2], wxr[4][2], wor[2];
    #pragma unroll
    for (int g = 0; g < 4; g++){
        b1r[g][0] = (j0 < Hh) ? (bih1[g*Hh + j0] + bhh1[g*Hh + j0]) : 0.f;
        b1r[g][1] = (j1 < Hh) ? (bih1[g*Hh + j1] + bhh1[g*Hh + j1]) : 0.f;
        b2r[g][0] = (j0 < Hh) ? (bih2[g*Hh + j0] + bhh2[g*Hh + j0]) : 0.f;
        b2r[g][1] = (j1 < Hh) ? (bih2[g*Hh + j1] + bhh2[g*Hh + j1]) : 0.f;
        wxr[g][0] = (j0 < Hh) ? Wih1[g*Hh + j0] : 0.f;
        wxr[g][1] = (j1 < Hh) ? Wih1[g*Hh + j1] : 0.f;
    }
    wor[0] = (j0 < Hh) ? Wout[j0] : 0.f;
    wor[1] = (j1 < Hh) ? Wout[j1] : 0.f;

    float c1[2][2][2];
    #pragma unroll
    for (int a = 0; a < 2; a++)
        #pragma unroll
        for (int b = 0; b < 2; b++)
            #pragma unroll
            for (int c = 0; c < 2; c++) c1[a][b][c] = 0.f;

    float bo = *bout;
    bool ywarp = (jt == 0);
    int ym = pw*32 + lane;
    uint32_t wH = sb + OFF_WH, wL = sb + OFF_WL;

    // ======================= sequence phase: 1 barrier/step =======================
    for (int k = 0; k < Tt; k++){
        int rb = (k+1)&1, wb = k&1;
        uint32_t aHr = sb + OFF_A + (rb*2+0)*ATILE;
        uint32_t aLr = sb + OFF_A + (rb*2+1)*ATILE;
        int aHw = OFF_A + (wb*2+0)*ATILE;
        int aLw = OFF_A + (wb*2+1)*ATILE;

        // y-warps: deferred y(k-2) combine + x(k+1) prefetch
        if (ywarp){
            if (k >= 2){
                float y = bo;
                #pragma unroll
                for (int q = 0; q < 7; q++)
                    y += parts[rb*448 + (pw*7 + q)*32 + lane];
                if (ym < nb) out[(size_t)(bstart + ym)*OTot + (k-2)] = y;
            }
            if (k + 1 < Tt){
                float xv = (ym < nb) ? __ldg(&x[(size_t)(bstart + ym)*Tt + k + 1]) : 0.f;
                xs[rb*64 + ym] = xv;
            }
        }

        float D[2][4][4];

        // ---- emit GEMM (step k-1) + partials ----
        if (k > 0){
            layer_mma<1>(D, aHr, aLr, wH, wL, pw, jt, lane);
            #pragma unroll
            for (int cb = 0; cb < 2; cb++){
                float plo = 0.f, phi = 0.f;
                #pragma unroll
                for (int hf = 0; hf < 2; hf++){
                    #pragma unroll
                    for (int jc = 0; jc < 2; jc++){
                        int e = hf*2 + jc;
                        float gi = D[cb][0][e] + b2r[0][jc];
                        float gf = D[cb][1][e] + b2r[1][jc];
                        float gg = D[cb][2][e] + b2r[2][jc];
                        float go = D[cb][3][e] + b2r[3][jc];
                        float c2 = sigm(gf)*c1[cb][hf][jc] + sigm(gi)*tanh_f(gg);
                        float v  = sigm(go)*tanh_f(c2) * wor[jc];
                        if (hf) phi += v; else plo += v;
                    }
                }
                plo += __shfl_xor_sync(0xffffffffu, plo, 1);
                plo += __shfl_xor_sync(0xffffffffu, plo, 2);
                phi += __shfl_xor_sync(0xffffffffu, phi, 1);
                phi += __shfl_xor_sync(0xffffffffu, phi, 2);
                if ((lane & 3) == 0){
                    parts[wb*448 + w*32 + cb*16 + rgrp]     = plo;
                    parts[wb*448 + w*32 + cb*16 + 8 + rgrp] = phi;
                }
            }
        }

        // ---- layer-1 GEMM (step k) + cell update ----
        layer_mma<0>(D, aHr, aLr, wH, wL, pw, jt, lane);
        #pragma unroll
        for (int cb = 0; cb < 2; cb++){
            int mbase = (pw*2 + cb)*16 + rgrp;
            #pragma unroll
            for (int hf = 0; hf < 2; hf++){
                int m = mbase + hf*8;
                float xm = xs[wb*64 + m];
                #pragma unroll
                for (int jc = 0; jc < 2; jc++){
                    int e = hf*2 + jc;
                    float gi = D[cb][0][e] + b1r[0][jc] + wxr[0][jc]*xm;
                    float gf = D[cb][1][e] + b1r[1][jc] + wxr[1][jc]*xm;
                    float gg = D[cb][2][e] + b1r[2][jc] + wxr[2][jc]*xm;
                    float go = D[cb][3][e] + b1r[3][jc] + wxr[3][jc]*xm;
                    float cn = sigm(gf)*c1[cb][hf][jc] + sigm(gi)*tanh_f(gg);
                    c1[cb][hf][jc] = cn;
                    float hp = sigm(go)*tanh_f(cn);
                    int j = jc ? j1 : j0;
                    split_sts(smem, aHw, aLw, (uint32_t)(m*SPB + j*2), hp);
                }
            }
        }
        __syncthreads();
    }

    // ======================= future phase: autoregressive =======================
    for (int k = Tt; k < OTot; k++){
        int rb = (k+1)&1, wb = k&1;
        uint32_t aHr = sb + OFF_A + (rb*2+0)*ATILE;
        uint32_t aLr = sb + OFF_A + (rb*2+1)*ATILE;
        int aHw = OFF_A + (wb*2+0)*ATILE;
        int aLw = OFF_A + (wb*2+1)*ATILE;

        float D[2][4][4];
        layer_mma<1>(D, aHr, aLr, wH, wL, pw, jt, lane);
        #pragma unroll
        for (int cb = 0; cb < 2; cb++){
            float plo = 0.f, phi = 0.f;
            #pragma unroll
            for (int hf = 0; hf < 2; hf++){
                #pragma unroll
                for (int jc = 0; jc < 2; jc++){
                    int e = hf*2 + jc;
                    float gi = D[cb][0][e] + b2r[0][jc];
                    float gf = D[cb][1][e] + b2r[1][jc];
                    float gg = D[cb][2][e] + b2r[2][jc];
                    float go = D[cb][3][e] + b2r[3][jc];
                    float c2 = sigm(gf)*c1[cb][hf][jc] + sigm(gi)*tanh_f(gg);
                    float v  = sigm(go)*tanh_f(c2) * wor[jc];
                    if (hf) phi += v; else plo += v;
                }
            }
            plo += __shfl_xor_sync(0xffffffffu, plo, 1);
            plo += __shfl_xor_sync(0xffffffffu, plo, 2);
            phi += __shfl_xor_sync(0xffffffffu, phi, 1);
            phi += __shfl_xor_sync(0xffffffffu, phi, 2);
            if ((lane & 3) == 0){
                parts[wb*448 + w*32 + cb*16 + rgrp]     = plo;
                parts[wb*448 + w*32 + cb*16 + 8 + rgrp] = phi;
            }
        }
        // boundary: deferred y(Tt-2) still pending at k==Tt
        if (k == Tt && ywarp){
            float y = bo;
            #pragma unroll
            for (int q = 0; q < 7; q++)
                y += parts[rb*448 + (pw*7 + q)*32 + lane];
            if (ym < nb) out[(size_t)(bstart + ym)*OTot + (k-2)] = y;
        }
        __syncthreads();

        if (ywarp){
            float y = bo;
            #pragma unroll
            for (int q = 0; q < 7; q++)
                y += parts[wb*448 + (pw*7 + q)*32 + lane];
            if (ym < nb) out[(size_t)(bstart + ym)*OTot + (k-1)] = y;
            xs[wb*64 + ym] = y;            // x(k) feedback
        }
        __syncthreads();

        layer_mma<0>(D, aHr, aLr, wH, wL, pw, jt, lane);
        #pragma unroll
        for (int cb = 0; cb < 2; cb++){
            int mbase = (pw*2 + cb)*16 + rgrp;
            #pragma unroll
            for (int hf = 0; hf < 2; hf++){
                int m = mbase + hf*8;
                float xm = xs[wb*64 + m];
                #pragma unroll
                for (int jc = 0; jc < 2; jc++){
                    int e = hf*2 + jc;
                    float gi = D[cb][0][e] + b1r[0][jc] + wxr[0][jc]*xm;
                    float gf = D[cb][1][e] + b1r[1][jc] + wxr[1][jc]*xm;
                    float gg = D[cb][2][e] + b1r[2][jc] + wxr[2][jc]*xm;
                    float go = D[cb][3][e] + b1r[3][jc] + wxr[3][jc]*xm;
                    float cn = sigm(gf)*c1[cb][hf][jc] + sigm(gi)*tanh_f(gg);
                    c1[cb][hf][jc] = cn;
                    float hp = sigm(go)*tanh_f(cn);
                    int j = jc ? j1 : j0;
                    split_sts(smem, aHw, aLw, (uint32_t)(m*SPB + j*2), hp);
                }
            }
        }
        __syncthreads();
    }

    // ======================= tail: emit y(OTot-1) =======================
    {
        int k = OTot;
        int rb = (k+1)&1, wb = k&1;
        uint32_t aHr = sb + OFF_A + (rb*2+0)*ATILE;
        uint32_t aLr = sb + OFF_A + (rb*2+1)*ATILE;
        float D[2][4][4];
        layer_mma<1>(D, aHr, aLr, wH, wL, pw, jt, lane);
        #pragma unroll
        for (int cb = 0; cb < 2; cb++){
            float plo = 0.f, phi = 0.f;
            #pragma unroll
            for (int hf = 0; hf < 2; hf++){
                #pragma unroll
                for (int jc = 0; jc < 2; jc++){
                    int e = hf*2 + jc;
                    float gi = D[cb][0][e] + b2r[0][jc];
                    float gf = D[cb][1][e] + b2r[1][jc];
                    float gg = D[cb][2][e] + b2r[2][jc];
                    float go = D[cb][3][e] + b2r[3][jc];
                    float c2 = sigm(gf)*c1[cb][hf][jc] + sigm(gi)*tanh_f(gg);
                    float v  = sigm(go)*tanh_f(c2) * wor[jc];
                    if (hf) phi += v; else plo += v;
                }
            }
            plo += __shfl_xor_sync(0xffffffffu, plo, 1);
            plo += __shfl_xor_sync(0xffffffffu, plo, 2);
            phi += __shfl_xor_sync(0xffffffffu, phi, 1);
            phi += __shfl_xor_sync(0xffffffffu, phi, 2);
            if ((lane & 3) == 0){
                parts[wb*448 + w*32 + cb*16 + rgrp]     = plo;
                parts[wb*448 + w*32 + cb*16 + 8 + rgrp] = phi;
            }
        }
        __syncthreads();
        if (ywarp){
            float y = bo;
            #pragma unroll
            for (int q = 0; q < 7; q++)
                y += parts[wb*448 + (pw*7 + q)*32 + lane];
            if (ym < nb) out[(size_t)(bstart + ym)*OTot + (OTot-1)] = y;
        }
    }
}

extern "C" void kernel_launch(void* const* d_in, const int* in_sizes, int n_in,
                              void* d_out, int out_size)
{
    const float* x    = (const float*)d_in[0];
    const float* Wih1 = (const float*)d_in[1];
    const float* Whh1 = (const float*)d_in[2];
    const float* bih1 = (const float*)d_in[3];
    const float* bhh1 = (const float*)d_in[4];
    const float* Wih2 = (const float*)d_in[5];
    const float* Whh2 = (const float*)d_in[6];
    const float* bih2 = (const float*)d_in[7];
    const float* bhh2 = (const float*)d_in[8];
    const float* Wout = (const float*)d_in[9];
    const float* bout = (const float*)d_in[10];
    float* out = (float*)d_out;

    cudaFuncSetAttribute(lstm_hmma_kernel,
                         cudaFuncAttributeMaxDynamicSharedMemorySize, SMEM_BYTES);

    lstm_hmma_kernel<<<GRID, TPB, SMEM_BYTES>>>(
        x, Wih1, Whh1, bih1, bhh1, Wih2, Whh2, bih2, bhh2, Wout, bout, out);
}